// round 8
// baseline (speedup 1.0000x reference)
#include <cuda_runtime.h>
#include <cuda_bf16.h>
#include <cstdint>

// GRU seq2seq via mma.sync bf16 hi/lo split. Round 8: 512 thr/CTA, 3-stage
// cp.async ring, 1 barrier per K-chunk.
// B=512, S=128, P=32, F=O=64, H=1024, IN=128, K=1152, 159 steps.

#define B_    512
#define S_    128
#define P_    32
#define F_    64
#define O_    64
#define H_    1024
#define IN_   128
#define KTOT  1152
#define TTOT  159
#define BM    128
#define BN    32
#define NCH   36      // K chunks of 32
#define XCH   4       // first 4 chunks = x-part (K=128)
#define NSTG  3

// stage layout (bytes)
#define A_HI 0
#define A_LO 8192
#define B_HI 16384
#define B_LO 22528
#define STAGE 28672
#define SMEM_DYN (NSTG * STAGE)

typedef __nv_bfloat16 bf16;

// ---------------- device scratch --------------------------------------------
__device__ bf16  g_x_hi[TTOT][B_][IN_];
__device__ bf16  g_x_lo[TTOT][B_][IN_];
__device__ bf16  g_w_hi[3 * H_][KTOT];
__device__ bf16  g_w_lo[3 * H_][KTOT];
__device__ float g_h[2][B_][H_];
__device__ bf16  g_h_hi[2][B_][H_];
__device__ bf16  g_h_lo[2][B_][H_];
__device__ float g_Wdt[H_][O_];
__device__ float g_brz[2 * H_];
__device__ float g_bin[H_];
__device__ float g_bhn[H_];

// ---------------- helpers ----------------------------------------------------
__device__ __forceinline__ uint32_t smem_u32(const void* p) {
    uint32_t a;
    asm("{ .reg .u64 t; cvta.to.shared.u64 t, %1; cvt.u32.u64 %0, t; }"
        : "=r"(a) : "l"(p));
    return a;
}
__device__ __forceinline__ void cp16(uint32_t dst, const void* src) {
    asm volatile("cp.async.cg.shared.global [%0], [%1], 16;"
                 :: "r"(dst), "l"(src) : "memory");
}
__device__ __forceinline__ void cp_commit() {
    asm volatile("cp.async.commit_group;" ::: "memory");
}
template<int N>
__device__ __forceinline__ void cp_wait() {
    asm volatile("cp.async.wait_group %0;" :: "n"(N) : "memory");
}
__device__ __forceinline__ void ldsm4(uint32_t* r, uint32_t addr) {
    asm volatile("ldmatrix.sync.aligned.m8n8.x4.shared.b16 "
                 "{%0,%1,%2,%3}, [%4];"
                 : "=r"(r[0]), "=r"(r[1]), "=r"(r[2]), "=r"(r[3])
                 : "r"(addr));
}
__device__ __forceinline__ void ldsm2(uint32_t* r, uint32_t addr) {
    asm volatile("ldmatrix.sync.aligned.m8n8.x2.shared.b16 "
                 "{%0,%1}, [%2];"
                 : "=r"(r[0]), "=r"(r[1])
                 : "r"(addr));
}
__device__ __forceinline__ void mma16816(float* c, const uint32_t* a,
                                         uint32_t b0, uint32_t b1) {
    asm volatile(
        "mma.sync.aligned.m16n8k16.row.col.f32.bf16.bf16.f32 "
        "{%0,%1,%2,%3}, {%4,%5,%6,%7}, {%8,%9}, {%0,%1,%2,%3};"
        : "+f"(c[0]), "+f"(c[1]), "+f"(c[2]), "+f"(c[3])
        : "r"(a[0]), "r"(a[1]), "r"(a[2]), "r"(a[3]), "r"(b0), "r"(b1));
}
// 16B-chunk XOR swizzle within 64B rows (conflict-free ldmatrix phases)
__device__ __forceinline__ uint32_t swz(int row, int kc) {
    return (uint32_t)(row * 64 + ((kc ^ ((row >> 1) & 3)) << 4));
}
__device__ __forceinline__ float sigf(float x)  { return 1.f / (1.f + __expf(-x)); }
__device__ __forceinline__ float tanhf_(float x){ return 1.f - 2.f / (1.f + __expf(2.f * x)); }

// ---------------- pack kernel ------------------------------------------------
__global__ void pack_kernel(const float* __restrict__ feats,
                            const float* __restrict__ labels,
                            const float* __restrict__ Wi,
                            const float* __restrict__ Wh,
                            const float* __restrict__ bi,
                            const float* __restrict__ bh,
                            const float* __restrict__ Wd) {
    long idx = (long)blockIdx.x * 256 + threadIdx.x;
    const long N1 = (long)TTOT * B_ * F_;
    const long N2 = (long)S_ * B_ * O_;
    const long N3 = (long)3 * H_ * KTOT;
    const long N4 = (long)B_ * H_;
    const long N5 = (long)H_ * O_;
    const long N6 = 4096;
    if (idx < N1) {
        int t = (int)(idx / (B_ * F_));
        int r = (int)(idx % (B_ * F_));
        int b = r / F_, c = r % F_;
        float v = feats[((long)b * TTOT + t) * F_ + c];
        bf16 h = __float2bfloat16(v);
        g_x_hi[t][b][c] = h;
        g_x_lo[t][b][c] = __float2bfloat16(v - __bfloat162float(h));
        return;
    }
    idx -= N1;
    if (idx < N2) {
        int t = (int)(idx / (B_ * O_));
        int r = (int)(idx % (B_ * O_));
        int b = r / O_, c = r % O_;
        float v = labels[((long)b * S_ + t) * O_ + c];
        bf16 h = __float2bfloat16(v);
        g_x_hi[t][b][F_ + c] = h;
        g_x_lo[t][b][F_ + c] = __float2bfloat16(v - __bfloat162float(h));
        return;
    }
    idx -= N2;
    if (idx < N3) {
        int n = (int)(idx / KTOT), k = (int)(idx % KTOT);
        float v = (k < IN_) ? Wi[(long)n * IN_ + k]
                            : Wh[(long)n * H_ + (k - IN_)];
        bf16 h = __float2bfloat16(v);
        g_w_hi[n][k] = h;
        g_w_lo[n][k] = __float2bfloat16(v - __bfloat162float(h));
        return;
    }
    idx -= N3;
    if (idx < N4) {
        int b = (int)(idx / H_), j = (int)(idx % H_);
        g_h[0][b][j] = 0.f;
        g_h_hi[0][b][j] = __float2bfloat16(0.f);
        g_h_lo[0][b][j] = __float2bfloat16(0.f);
        return;
    }
    idx -= N4;
    if (idx < N5) {
        int k = (int)(idx / O_), o = (int)(idx % O_);
        g_Wdt[k][o] = Wd[(long)o * H_ + k];
        return;
    }
    idx -= N5;
    if (idx < N6) {
        int i = (int)idx;
        if (i < 2048)      g_brz[i] = bi[i] + bh[i];
        else if (i < 3072) g_bin[i - 2048] = bi[i];
        else               g_bhn[i - 3072] = bh[i - 1024];
    }
}

// ---------------- compute one K-chunk (2 k16 steps) --------------------------
// G2 = accumulator group for the n-gate this chunk (2 = IN, 3 = HN).
template<int G2>
__device__ __forceinline__ void compute_chunk(
    const char* st, int lane, int mw, int nw, float (&acc)[4][2][4])
{
    const uint32_t ab = smem_u32(st + A_HI);
    const uint32_t bb = smem_u32(st + B_HI);
    #pragma unroll
    for (int ks = 0; ks < 2; ++ks) {
        uint32_t Ah[2][4], Al[2][4];
        #pragma unroll
        for (int mi = 0; mi < 2; ++mi) {
            const int arow = mw * 32 + mi * 16 + (lane & 15);
            const int kc = ks * 2 + (lane >> 4);
            const uint32_t off = swz(arow, kc);
            ldsm4(Ah[mi], ab + off);
            ldsm4(Al[mi], ab + (A_LO - A_HI) + off);
        }
        #pragma unroll
        for (int g = 0; g < 3; ++g) {
            const int grp = (g == 2) ? G2 : g;
            const int brow = g * 32 + nw * 8 + (lane & 7);
            const int kc = ks * 2 + ((lane >> 3) & 1);
            const uint32_t off = swz(brow, kc);
            uint32_t Bh[2], Bl[2];
            ldsm2(Bh, bb + off);
            ldsm2(Bl, bb + (B_LO - B_HI) + off);
            #pragma unroll
            for (int mi = 0; mi < 2; ++mi) {
                float* C = acc[grp][mi];
                mma16816(C, Ah[mi], Bh[0], Bh[1]);
                mma16816(C, Al[mi], Bh[0], Bh[1]);
                mma16816(C, Ah[mi], Bl[0], Bl[1]);
            }
        }
    }
}

// ---------------- fused GRU step (mma.sync) ----------------------------------
__global__ __launch_bounds__(512)
void gru_step_mma(int t, int cur) {
    extern __shared__ char sm[];
    const int tid = threadIdx.x;
    const int lane = tid & 31, wid = tid >> 5;
    const int mw = wid & 3, nw = wid >> 2;     // 4 x 4 warp grid
    const int bm0 = blockIdx.x * BM;
    const int bn0 = blockIdx.y * BN;
    const int nxt = cur ^ 1;

    float acc[4][2][4];
    #pragma unroll
    for (int a = 0; a < 4; ++a)
        #pragma unroll
        for (int b = 0; b < 2; ++b)
            #pragma unroll
            for (int d = 0; d < 4; ++d) acc[a][b][d] = 0.f;

    // ---- async chunk loader (512 threads, 1792 cp16 per chunk) ----
    auto load_chunk = [&](int ch, char* st) {
        const int k0 = ch * 32;
        #pragma unroll
        for (int i = 0; i < 4; ++i) {
            const int c = tid + i * 512;     // 0..2047
            if (c < 1024) {
                const int term = c >> 9;
                const int rem = c & 511;
                const int row = rem >> 2, kc = rem & 3;
                const bf16* src;
                if (ch < XCH) {
                    const bf16* base = term ? &g_x_lo[t][0][0] : &g_x_hi[t][0][0];
                    src = base + (long)(bm0 + row) * IN_ + k0 + kc * 8;
                } else {
                    const bf16* base = term ? &g_h_lo[cur][0][0]
                                            : &g_h_hi[cur][0][0];
                    src = base + (long)(bm0 + row) * H_ + (k0 - IN_) + kc * 8;
                }
                cp16(smem_u32(st + (term ? A_LO : A_HI)) + swz(row, kc), src);
            } else if (c < 1792) {
                const int c2 = c - 1024;
                const int term = (c2 >= 384);
                const int rem = c2 - term * 384;
                const int row = rem >> 2, kc = rem & 3;
                const int grow = (row >> 5) * H_ + bn0 + (row & 31);
                const bf16* base = term ? &g_w_lo[0][0] : &g_w_hi[0][0];
                const bf16* src = base + (long)grow * KTOT + k0 + kc * 8;
                cp16(smem_u32(st + (term ? B_LO : B_HI)) + swz(row, kc), src);
            }
        }
    };

    // prologue: stages 0,1
    load_chunk(0, sm);
    cp_commit();
    load_chunk(1, sm + STAGE);
    cp_commit();

    int cs = 0, ls = 2;   // compute-stage / load-stage indices
    for (int ch = 0; ch < NCH; ++ch) {
        if (ch < NCH - 1) cp_wait<1>(); else cp_wait<0>();
        __syncthreads();
        const char* st = sm + cs * STAGE;
        if (ch < XCH) compute_chunk<2>(st, lane, mw, nw, acc);
        else          compute_chunk<3>(st, lane, mw, nw, acc);
        if (ch + 2 < NCH) {
            load_chunk(ch + 2, sm + ls * STAGE);
            cp_commit();
        }
        cs = (cs + 1 == NSTG) ? 0 : cs + 1;
        ls = (ls + 1 == NSTG) ? 0 : ls + 1;
    }

    // ---- epilogue: gates + state update (all in-register) ----
    const int l4 = lane >> 2;
    const int l2 = (lane & 3) * 2;
    const int j0 = bn0 + nw * 8 + l2;
    #pragma unroll
    for (int mi = 0; mi < 2; ++mi) {
        #pragma unroll
        for (int rh = 0; rh < 2; ++rh) {
            const int b = bm0 + mw * 32 + mi * 16 + l4 + rh * 8;
            const float2 hold = *(const float2*)&g_h[cur][b][j0];
            float hv[2]; bf16 hh[2], hl[2];
            #pragma unroll
            for (int u = 0; u < 2; ++u) {
                const int j = j0 + u;
                const int ai = rh * 2 + u;
                float rv = sigf(acc[0][mi][ai] + g_brz[j]);
                float zv = sigf(acc[1][mi][ai] + g_brz[H_ + j]);
                float nv = tanhf_(acc[2][mi][ai] + g_bin[j] +
                                  rv * (acc[3][mi][ai] + g_bhn[j]));
                float ho = (u == 0) ? hold.x : hold.y;
                float v = nv + zv * (ho - nv);
                hv[u] = v;
                hh[u] = __float2bfloat16(v);
                hl[u] = __float2bfloat16(v - __bfloat162float(hh[u]));
            }
            *(float2*)&g_h[nxt][b][j0] = make_float2(hv[0], hv[1]);
            *(uint32_t*)&g_h_hi[nxt][b][j0] = *(uint32_t*)hh;
            *(uint32_t*)&g_h_lo[nxt][b][j0] = *(uint32_t*)hl;
        }
    }
}

// ---------------- ps = h @ Wd.T + bd ----------------------------------------
__global__ __launch_bounds__(256)
void ps_kernel(int cur, const float* __restrict__ bd,
               float* __restrict__ out_slot, int xslot)
{
    __shared__ float hsm[4][H_];
    __shared__ float red[4][4][O_];
    const int tid = threadIdx.x;
    const int o = tid % 64;
    const int s = tid / 64;
    const int b0 = blockIdx.x * 4;
    const float* h = &g_h[cur][0][0];

    for (int i = tid; i < 4 * H_; i += 256) {
        int bb = i / H_, k = i % H_;
        hsm[bb][k] = h[(b0 + bb) * H_ + k];
    }
    __syncthreads();

    float a0 = 0.f, a1 = 0.f, a2 = 0.f, a3 = 0.f;
    const int k0 = s * (H_ / 4);
    for (int k = k0; k < k0 + (H_ / 4); ++k) {
        float w = g_Wdt[k][o];
        a0 += hsm[0][k] * w;
        a1 += hsm[1][k] * w;
        a2 += hsm[2][k] * w;
        a3 += hsm[3][k] * w;
    }
    red[s][0][o] = a0; red[s][1][o] = a1;
    red[s][2][o] = a2; red[s][3][o] = a3;
    __syncthreads();

    if (s == 0) {
        #pragma unroll
        for (int bb = 0; bb < 4; ++bb) {
            float v = red[0][bb][o] + red[1][bb][o] +
                      red[2][bb][o] + red[3][bb][o] + bd[o];
            out_slot[(b0 + bb) * O_ + o] = v;
            if (xslot >= 0) {
                bf16 h2 = __float2bfloat16(v);
                g_x_hi[xslot][b0 + bb][F_ + o] = h2;
                g_x_lo[xslot][b0 + bb][F_ + o] =
                    __float2bfloat16(v - __bfloat162float(h2));
            }
        }
    }
}

// ---------------- launch -----------------------------------------------------
extern "C" void kernel_launch(void* const* d_in, const int* in_sizes, int n_in,
                              void* d_out, int out_size)
{
    const float* feats  = (const float*)d_in[0];
    const float* labels = (const float*)d_in[1];
    const float* Wi     = (const float*)d_in[2];
    const float* Wh     = (const float*)d_in[3];
    const float* bi     = (const float*)d_in[4];
    const float* bh     = (const float*)d_in[5];
    const float* Wd     = (const float*)d_in[6];
    const float* bd     = (const float*)d_in[7];
    float* out = (float*)d_out;

    cudaFuncSetAttribute(gru_step_mma,
                         cudaFuncAttributeMaxDynamicSharedMemorySize, SMEM_DYN);

    {
        const long total = (long)TTOT * B_ * F_ + (long)S_ * B_ * O_ +
                           (long)3 * H_ * KTOT + (long)B_ * H_ +
                           (long)H_ * O_ + 4096;
        const int blocks = (int)((total + 255) / 256);
        pack_kernel<<<blocks, 256>>>(feats, labels, Wi, Wh, bi, bh, Wd);
    }

    dim3 grid(B_ / BM, H_ / BN);   // 4 x 32 = 128 CTAs
    int cur = 0;

    for (int t = 0; t < S_; ++t) {
        gru_step_mma<<<grid, 512, SMEM_DYN>>>(t, cur);
        cur ^= 1;
    }
    ps_kernel<<<B_ / 4, 256>>>(cur, bd, out, S_);

    for (int i = 0; i < P_ - 1; ++i) {
        gru_step_mma<<<grid, 512, SMEM_DYN>>>(S_ + i, cur);
        cur ^= 1;
        ps_kernel<<<B_ / 4, 256>>>(cur, bd,
                                   out + (long)(i + 1) * B_ * O_,
                                   (i < P_ - 2) ? (S_ + 1 + i) : -1);
    }
}